// round 1
// baseline (speedup 1.0000x reference)
#include <cuda_runtime.h>
#include <math.h>

// Problem constants
#define BB   8
#define SS   4
#define TT   2048
#define LL   2
#define NH   32
#define NKV  8
#define HD   128
#define DIM  4096
#define NHHD 4096     // NH*HD
#define KVD  1024     // NKV*HD
#define MM   32       // B*S
#define SPLIT 4
#define QK_SCALE 0.08838834764831845f  // 1/sqrt(128)

// ---------------- scratch (device globals; no allocations allowed) ----------------
__device__ float g_q2[SPLIT * MM * NHHD];   // split-K partials for xq
__device__ float g_k2[SPLIT * MM * KVD];    // split-K partials for xk
__device__ float g_v2[SPLIT * MM * KVD];    // split-K partials for xv
__device__ float g_q[MM * NHHD];            // roped + scaled q
__device__ float g_k[MM * KVD];             // roped k (new tokens)
__device__ float g_v[MM * KVD];             // v (new tokens)
__device__ float g_attn[MM * NHHD];         // attention output (pre-projection)
__device__ float g_o2[SPLIT * MM * DIM];    // split-K partials for output proj

// ---------------- fp32 tiled GEMM body: C[32 x N] = A[32 x 4096] * W[N x 4096]^T ----
// BM=32, BN=64, BK=32, 128 threads, 4x4 micro-tile per thread.
// Smem tiles stored transposed ([kk][m] / [kk][n]) so the inner loop is 2x LDS.128.
__device__ __forceinline__ void gemm_body(const float* __restrict__ A,
                                          const float* __restrict__ W,
                                          float* __restrict__ C,
                                          int N, int n0, int k0, int kLen)
{
    __shared__ __align__(16) float As[32][36];   // [kk][m], pad keeps 16B alignment
    __shared__ __align__(16) float Ws[32][68];   // [kk][n]

    const int tid = threadIdx.x;           // 0..127
    const int tx  = tid & 15;              // n group
    const int ty  = tid >> 4;              // m group (0..7)
    const int m0  = ty * 4;
    const int nn  = tx * 4;

    float acc[4][4];
#pragma unroll
    for (int i = 0; i < 4; i++)
#pragma unroll
        for (int j = 0; j < 4; j++) acc[i][j] = 0.f;

    const int r  = tid >> 3;               // 0..15
    const int c4 = (tid & 7) * 4;          // 0..28

    for (int kt = k0; kt < k0 + kLen; kt += 32) {
        // load A tile (32x32): 2 float4 per thread, coalesced
#pragma unroll
        for (int jj = 0; jj < 2; jj++) {
            int row = r + 16 * jj;
            float4 a = *(const float4*)(A + (long)row * 4096 + kt + c4);
            As[c4 + 0][row] = a.x; As[c4 + 1][row] = a.y;
            As[c4 + 2][row] = a.z; As[c4 + 3][row] = a.w;
        }
        // load W tile (64x32): 4 float4 per thread, coalesced
#pragma unroll
        for (int jj = 0; jj < 4; jj++) {
            int row = r + 16 * jj;
            float4 w = *(const float4*)(W + (long)(n0 + row) * 4096 + kt + c4);
            Ws[c4 + 0][row] = w.x; Ws[c4 + 1][row] = w.y;
            Ws[c4 + 2][row] = w.z; Ws[c4 + 3][row] = w.w;
        }
        __syncthreads();

#pragma unroll
        for (int kk = 0; kk < 32; kk++) {
            float4 a4 = *(const float4*)&As[kk][m0];
            float4 w4 = *(const float4*)&Ws[kk][nn];
            float av[4] = {a4.x, a4.y, a4.z, a4.w};
            float wv[4] = {w4.x, w4.y, w4.z, w4.w};
#pragma unroll
            for (int i = 0; i < 4; i++)
#pragma unroll
                for (int j = 0; j < 4; j++)
                    acc[i][j] = fmaf(av[i], wv[j], acc[i][j]);
        }
        __syncthreads();
    }

#pragma unroll
    for (int i = 0; i < 4; i++)
#pragma unroll
        for (int j = 0; j < 4; j++)
            C[(long)(m0 + i) * N + n0 + nn + j] = acc[i][j];
}

// ---------------- kernel 1: fused QKV projection (split-K partials) ----------------
__global__ void __launch_bounds__(128) qkv_gemm(const float* __restrict__ x,
                                                const float* __restrict__ wq,
                                                const float* __restrict__ wk,
                                                const float* __restrict__ wv)
{
    const int bx = blockIdx.x;         // 0..95
    const int sp = blockIdx.y;         // 0..SPLIT-1
    const int k0 = sp * (4096 / SPLIT);
    const int kl = 4096 / SPLIT;
    if (bx < 64) {
        gemm_body(x, wq, g_q2 + (long)sp * MM * NHHD, NHHD, bx * 64, k0, kl);
    } else if (bx < 80) {
        gemm_body(x, wk, g_k2 + (long)sp * MM * KVD, KVD, (bx - 64) * 64, k0, kl);
    } else {
        gemm_body(x, wv, g_v2 + (long)sp * MM * KVD, KVD, (bx - 80) * 64, k0, kl);
    }
}

// ---------------- kernel 2: split-K reduce + RoPE (+ q scaling) --------------------
__global__ void __launch_bounds__(256) combine_qkv_rope(const float* __restrict__ angles)
{
    const int idx = blockIdx.x * 256 + threadIdx.x;   // 0..114687
    const int QP = MM * NH * 64;    // 65536 q pairs
    const int KP = MM * NKV * 64;   // 16384 k pairs
    if (idx < QP) {
        int m = idx >> 11;           // /2048
        int h = (idx >> 6) & 31;
        int j = idx & 63;
        int off = m * NHHD + h * HD + 2 * j;
        float xr = 0.f, xi = 0.f;
#pragma unroll
        for (int s = 0; s < SPLIT; s++) {
            xr += g_q2[(long)s * MM * NHHD + off];
            xi += g_q2[(long)s * MM * NHHD + off + 1];
        }
        float a = angles[m * 64 + j];
        float c, sn; sincosf(a, &sn, &c);
        g_q[off]     = (xr * c - xi * sn) * QK_SCALE;
        g_q[off + 1] = (xr * sn + xi * c) * QK_SCALE;
    } else if (idx < QP + KP) {
        int p = idx - QP;
        int m = p >> 9;              // /512
        int kv = (p >> 6) & 7;
        int j = p & 63;
        int off = m * KVD + kv * HD + 2 * j;
        float xr = 0.f, xi = 0.f;
#pragma unroll
        for (int s = 0; s < SPLIT; s++) {
            xr += g_k2[(long)s * MM * KVD + off];
            xi += g_k2[(long)s * MM * KVD + off + 1];
        }
        float a = angles[m * 64 + j];
        float c, sn; sincosf(a, &sn, &c);
        g_k[off]     = xr * c - xi * sn;
        g_k[off + 1] = xr * sn + xi * c;
    } else {
        int e = idx - (QP + KP);
        if (e < MM * KVD) {
            float v = 0.f;
#pragma unroll
            for (int s = 0; s < SPLIT; s++) v += g_v2[(long)s * MM * KVD + e];
            g_v[e] = v;
        }
    }
}

// ---------------- kernel 3: flash attention, one block per (b, h) ------------------
__global__ void __launch_bounds__(256) attn_kernel(const float* __restrict__ cache_k,
                                                   const float* __restrict__ cache_v,
                                                   const float* __restrict__ mask,
                                                   const int* __restrict__ start_pos,
                                                   const int* __restrict__ layer_idx)
{
    __shared__ float q_s[SS * HD];            // 2 KB
    __shared__ float kt[32 * 129];            // 16.1 KB (pad 129: conflict-free both phases)
    __shared__ float vt[32 * 129];            // 16.1 KB
    __shared__ float p_s[SS * 32];            // scores for current tile
    __shared__ float m_run[SS], l_run[SS], scale_f[SS];

    const int b   = blockIdx.x >> 5;
    const int h   = blockIdx.x & 31;
    const int tid = threadIdx.x;
    const int li  = layer_idx[0];
    const int sp  = start_pos[b];
    const int kvh = h >> 2;                   // GQA repeat: head h -> kv head h/4

    // load q (already roped + scaled)
    for (int i = tid; i < SS * HD; i += 256)
        q_s[i] = g_q[(long)(b * SS + (i >> 7)) * NHHD + h * HD + (i & 127)];
    if (tid < SS) { m_run[tid] = -1e30f; l_run[tid] = 0.f; }

    // cache base for this (b, layer, head)
    const long base = (long)b * TT * LL * NHHD + (long)li * NHHD + (long)h * HD;
    const float* ckb = cache_k + base;
    const float* cvb = cache_v + base;
    const float* gkb = g_k + ((long)b * SS * NKV + kvh) * HD;  // + s*KVD per new row
    const float* gvb = g_v + ((long)b * SS * NKV + kvh) * HD;

    const int r  = tid >> 3;                  // tile row 0..31
    const int cb = (tid & 7) * 4;

    float acc0 = 0.f, acc1 = 0.f;
    const int d  = tid & 127;
    const int sb = (tid >> 7) * 2;            // thread owns s = sb, sb+1

    for (int t0 = 0; t0 < TT; t0 += 32) {
        __syncthreads();  // previous tile's consumers done before overwrite
        {
            int t = t0 + r;
            bool ovr = (t >= sp) && (t < sp + SS);
            const float* ksrc = ovr ? (gkb + (long)(t - sp) * KVD) : (ckb + (long)t * LL * NHHD);
            const float* vsrc = ovr ? (gvb + (long)(t - sp) * KVD) : (cvb + (long)t * LL * NHHD);
#pragma unroll
            for (int j = 0; j < 4; j++) {
                int c = cb + 32 * j;
                float4 kx = *(const float4*)(ksrc + c);
                float4 vx = *(const float4*)(vsrc + c);
                kt[r * 129 + c + 0] = kx.x; kt[r * 129 + c + 1] = kx.y;
                kt[r * 129 + c + 2] = kx.z; kt[r * 129 + c + 3] = kx.w;
                vt[r * 129 + c + 0] = vx.x; vt[r * 129 + c + 1] = vx.y;
                vt[r * 129 + c + 2] = vx.z; vt[r * 129 + c + 3] = vx.w;
            }
        }
        __syncthreads();

        // scores: 128 threads, one (s, t) each; q broadcast, k conflict-free
        if (tid < 128) {
            int s = tid >> 5, tl = tid & 31;
            const float* qp = q_s + s * HD;
            const float* kp = kt + tl * 129;
            float a = 0.f;
#pragma unroll 8
            for (int dd = 0; dd < HD; dd++) a = fmaf(qp[dd], kp[dd], a);
            p_s[s * 32 + tl] = a + mask[s * TT + t0 + tl];
        }
        __syncthreads();

        // online softmax: tile max + rescale factor
        if (tid < SS) {
            float mx = m_run[tid];
#pragma unroll
            for (int tl = 0; tl < 32; tl++) mx = fmaxf(mx, p_s[tid * 32 + tl]);
            scale_f[tid] = __expf(m_run[tid] - mx);
            m_run[tid] = mx;
        }
        __syncthreads();

        if (tid < 128) {
            int s = tid >> 5, tl = tid & 31;
            p_s[s * 32 + tl] = __expf(p_s[s * 32 + tl] - m_run[s]);
        }
        __syncthreads();

        if (tid < SS) {
            float sm = 0.f;
#pragma unroll
            for (int tl = 0; tl < 32; tl++) sm += p_s[tid * 32 + tl];
            l_run[tid] = l_run[tid] * scale_f[tid] + sm;
        }

        // PV accumulate: thread owns (sb, d) and (sb+1, d); v read once per t
        float f0 = scale_f[sb], f1 = scale_f[sb + 1];
        acc0 *= f0; acc1 *= f1;
#pragma unroll 8
        for (int tl = 0; tl < 32; tl++) {
            float v = vt[tl * 129 + d];
            acc0 = fmaf(p_s[sb * 32 + tl], v, acc0);
            acc1 = fmaf(p_s[(sb + 1) * 32 + tl], v, acc1);
        }
    }
    __syncthreads();

    g_attn[(long)(b * SS + sb)     * NHHD + h * HD + d] = acc0 / l_run[sb];
    g_attn[(long)(b * SS + sb + 1) * NHHD + h * HD + d] = acc1 / l_run[sb + 1];
}

// ---------------- kernel 4: output projection (split-K partials) -------------------
__global__ void __launch_bounds__(128) out_gemm(const float* __restrict__ wo)
{
    gemm_body(g_attn, wo, g_o2 + (long)blockIdx.y * MM * DIM, DIM,
              blockIdx.x * 64, blockIdx.y * (4096 / SPLIT), 4096 / SPLIT);
}

// ---------------- kernel 5: split-K reduce into output -----------------------------
__global__ void __launch_bounds__(256) combine_out(float* __restrict__ out)
{
    int idx = blockIdx.x * 256 + threadIdx.x;
    if (idx < MM * DIM) {
        float v = 0.f;
#pragma unroll
        for (int s = 0; s < SPLIT; s++) v += g_o2[(long)s * MM * DIM + idx];
        out[idx] = v;
    }
}

// ---------------- launch ------------------------------------------------------------
extern "C" void kernel_launch(void* const* d_in, const int* in_sizes, int n_in,
                              void* d_out, int out_size)
{
    const float* x         = (const float*)d_in[0];
    const int*   start_pos = (const int*)  d_in[1];
    const float* angles    = (const float*)d_in[2];
    const float* cache_k   = (const float*)d_in[3];
    const float* cache_v   = (const float*)d_in[4];
    const float* mask      = (const float*)d_in[5];
    const float* wq        = (const float*)d_in[6];
    const float* wk        = (const float*)d_in[7];
    const float* wv        = (const float*)d_in[8];
    const float* wo        = (const float*)d_in[9];
    const int*   layer_idx = (const int*)  d_in[10];
    float* out = (float*)d_out;

    qkv_gemm<<<dim3(96, SPLIT), 128>>>(x, wq, wk, wv);
    combine_qkv_rope<<<448, 256>>>(angles);
    attn_kernel<<<BB * NH, 256>>>(cache_k, cache_v, mask, start_pos, layer_idx);
    out_gemm<<<dim3(64, SPLIT), 128>>>(wo);
    combine_out<<<512, 256>>>(out);
}

// round 2
// speedup vs baseline: 1.3209x; 1.3209x over previous
#include <cuda_runtime.h>
#include <math.h>

// Problem constants
#define BB   8
#define SS   4
#define TT   2048
#define LL   2
#define NH   32
#define NKV  8
#define HD   128
#define DIM  4096
#define NHHD 4096     // NH*HD
#define KVD  1024     // NKV*HD
#define MM   32       // B*S
#define SPLIT 8
#define NCH  8        // attention T-dim chunks
#define CHT  (TT/NCH) // 256 tokens per chunk
#define QK_SCALE 0.08838834764831845f  // 1/sqrt(128)

// ---------------- scratch (device globals; no allocations allowed) ----------------
__device__ float g_q2[SPLIT * MM * NHHD];   // split-K partials for xq
__device__ float g_k2[SPLIT * MM * KVD];    // split-K partials for xk
__device__ float g_v2[SPLIT * MM * KVD];    // split-K partials for xv
__device__ float g_q[MM * NHHD];            // roped + scaled q
__device__ float g_k[MM * KVD];             // roped k (new tokens)
__device__ float g_v[MM * KVD];             // v (new tokens)
__device__ float g_attn[MM * NHHD];         // attention output (pre-projection)
__device__ float g_o2[SPLIT * MM * DIM];    // split-K partials for output proj
// attention split-T partials
__device__ float g_pm[BB * NH * NCH * SS];
__device__ float g_pl[BB * NH * NCH * SS];
__device__ float g_pa[BB * NH * NCH * SS * HD];

// ---------------- fp32 tiled GEMM body: C[32 x N] = A[32 x 4096] * W[N x 4096]^T ----
// BM=32, BN=64, BK=32, 128 threads, 4x4 micro-tile per thread.
__device__ __forceinline__ void gemm_body(const float* __restrict__ A,
                                          const float* __restrict__ W,
                                          float* __restrict__ C,
                                          int N, int n0, int k0, int kLen)
{
    __shared__ __align__(16) float As[32][36];   // [kk][m]
    __shared__ __align__(16) float Ws[32][68];   // [kk][n]

    const int tid = threadIdx.x;           // 0..127
    const int tx  = tid & 15;              // n group
    const int ty  = tid >> 4;              // m group (0..7)
    const int m0  = ty * 4;
    const int nn  = tx * 4;

    float acc[4][4];
#pragma unroll
    for (int i = 0; i < 4; i++)
#pragma unroll
        for (int j = 0; j < 4; j++) acc[i][j] = 0.f;

    const int r  = tid >> 3;               // 0..15
    const int c4 = (tid & 7) * 4;          // 0..28

    for (int kt = k0; kt < k0 + kLen; kt += 32) {
#pragma unroll
        for (int jj = 0; jj < 2; jj++) {
            int row = r + 16 * jj;
            float4 a = *(const float4*)(A + (long)row * 4096 + kt + c4);
            As[c4 + 0][row] = a.x; As[c4 + 1][row] = a.y;
            As[c4 + 2][row] = a.z; As[c4 + 3][row] = a.w;
        }
#pragma unroll
        for (int jj = 0; jj < 4; jj++) {
            int row = r + 16 * jj;
            float4 w = *(const float4*)(W + (long)(n0 + row) * 4096 + kt + c4);
            Ws[c4 + 0][row] = w.x; Ws[c4 + 1][row] = w.y;
            Ws[c4 + 2][row] = w.z; Ws[c4 + 3][row] = w.w;
        }
        __syncthreads();

#pragma unroll
        for (int kk = 0; kk < 32; kk++) {
            float4 a4 = *(const float4*)&As[kk][m0];
            float4 w4 = *(const float4*)&Ws[kk][nn];
            float av[4] = {a4.x, a4.y, a4.z, a4.w};
            float wv[4] = {w4.x, w4.y, w4.z, w4.w};
#pragma unroll
            for (int i = 0; i < 4; i++)
#pragma unroll
                for (int j = 0; j < 4; j++)
                    acc[i][j] = fmaf(av[i], wv[j], acc[i][j]);
        }
        __syncthreads();
    }

#pragma unroll
    for (int i = 0; i < 4; i++)
#pragma unroll
        for (int j = 0; j < 4; j++)
            C[(long)(m0 + i) * N + n0 + nn + j] = acc[i][j];
}

// ---------------- kernel 1: fused QKV projection (split-K partials) ----------------
__global__ void __launch_bounds__(128) qkv_gemm(const float* __restrict__ x,
                                                const float* __restrict__ wq,
                                                const float* __restrict__ wk,
                                                const float* __restrict__ wv)
{
    const int bx = blockIdx.x;         // 0..95
    const int sp = blockIdx.y;         // 0..SPLIT-1
    const int k0 = sp * (4096 / SPLIT);
    const int kl = 4096 / SPLIT;
    if (bx < 64) {
        gemm_body(x, wq, g_q2 + (long)sp * MM * NHHD, NHHD, bx * 64, k0, kl);
    } else if (bx < 80) {
        gemm_body(x, wk, g_k2 + (long)sp * MM * KVD, KVD, (bx - 64) * 64, k0, kl);
    } else {
        gemm_body(x, wv, g_v2 + (long)sp * MM * KVD, KVD, (bx - 80) * 64, k0, kl);
    }
}

// ---------------- kernel 2: split-K reduce + RoPE (+ q scaling) --------------------
__global__ void __launch_bounds__(256) combine_qkv_rope(const float* __restrict__ angles)
{
    const int idx = blockIdx.x * 256 + threadIdx.x;   // 0..114687
    const int QP = MM * NH * 64;    // 65536 q pairs
    const int KP = MM * NKV * 64;   // 16384 k pairs
    if (idx < QP) {
        int m = idx >> 11;
        int h = (idx >> 6) & 31;
        int j = idx & 63;
        int off = m * NHHD + h * HD + 2 * j;
        float xr = 0.f, xi = 0.f;
#pragma unroll
        for (int s = 0; s < SPLIT; s++) {
            xr += g_q2[(long)s * MM * NHHD + off];
            xi += g_q2[(long)s * MM * NHHD + off + 1];
        }
        float a = angles[m * 64 + j];
        float c, sn; sincosf(a, &sn, &c);
        g_q[off]     = (xr * c - xi * sn) * QK_SCALE;
        g_q[off + 1] = (xr * sn + xi * c) * QK_SCALE;
    } else if (idx < QP + KP) {
        int p = idx - QP;
        int m = p >> 9;
        int kv = (p >> 6) & 7;
        int j = p & 63;
        int off = m * KVD + kv * HD + 2 * j;
        float xr = 0.f, xi = 0.f;
#pragma unroll
        for (int s = 0; s < SPLIT; s++) {
            xr += g_k2[(long)s * MM * KVD + off];
            xi += g_k2[(long)s * MM * KVD + off + 1];
        }
        float a = angles[m * 64 + j];
        float c, sn; sincosf(a, &sn, &c);
        g_k[off]     = xr * c - xi * sn;
        g_k[off + 1] = xr * sn + xi * c;
    } else {
        int e = idx - (QP + KP);
        if (e < MM * KVD) {
            float v = 0.f;
#pragma unroll
            for (int s = 0; s < SPLIT; s++) v += g_v2[(long)s * MM * KVD + e];
            g_v[e] = v;
        }
    }
}

// ---------------- kernel 3: flash attention, block per (b, h, chunk) ---------------
__global__ void __launch_bounds__(256) attn_kernel(const float* __restrict__ cache_k,
                                                   const float* __restrict__ cache_v,
                                                   const float* __restrict__ mask,
                                                   const int* __restrict__ start_pos,
                                                   const int* __restrict__ layer_idx)
{
    __shared__ float q_s[SS * HD];            // 2 KB
    __shared__ float kt[32 * 129];            // conflict-free both phases
    __shared__ float vt[32 * 129];
    __shared__ float p_s[SS * 32];
    __shared__ float m_run[SS], l_run[SS], scale_f[SS];

    const int bh  = blockIdx.x;               // 0..255
    const int ch  = blockIdx.y;               // 0..NCH-1
    const int b   = bh >> 5;
    const int h   = bh & 31;
    const int tid = threadIdx.x;
    const int li  = layer_idx[0];
    const int sp  = start_pos[b];
    const int kvh = h >> 2;

    for (int i = tid; i < SS * HD; i += 256)
        q_s[i] = g_q[(long)(b * SS + (i >> 7)) * NHHD + h * HD + (i & 127)];
    if (tid < SS) { m_run[tid] = -1e30f; l_run[tid] = 0.f; }

    const long base = (long)b * TT * LL * NHHD + (long)li * NHHD + (long)h * HD;
    const float* ckb = cache_k + base;
    const float* cvb = cache_v + base;
    const float* gkb = g_k + ((long)b * SS * NKV + kvh) * HD;
    const float* gvb = g_v + ((long)b * SS * NKV + kvh) * HD;

    const int r  = tid >> 3;                  // tile row 0..31
    const int cb = (tid & 7) * 4;

    float acc0 = 0.f, acc1 = 0.f;
    const int d  = tid & 127;
    const int sb = (tid >> 7) * 2;

    const int t_lo = ch * CHT;
    const int t_hi = t_lo + CHT;

    for (int t0 = t_lo; t0 < t_hi; t0 += 32) {
        __syncthreads();
        {
            int t = t0 + r;
            bool ovr = (t >= sp) && (t < sp + SS);
            const float* ksrc = ovr ? (gkb + (long)(t - sp) * KVD) : (ckb + (long)t * LL * NHHD);
            const float* vsrc = ovr ? (gvb + (long)(t - sp) * KVD) : (cvb + (long)t * LL * NHHD);
#pragma unroll
            for (int j = 0; j < 4; j++) {
                int c = cb + 32 * j;
                float4 kx = *(const float4*)(ksrc + c);
                float4 vx = *(const float4*)(vsrc + c);
                kt[r * 129 + c + 0] = kx.x; kt[r * 129 + c + 1] = kx.y;
                kt[r * 129 + c + 2] = kx.z; kt[r * 129 + c + 3] = kx.w;
                vt[r * 129 + c + 0] = vx.x; vt[r * 129 + c + 1] = vx.y;
                vt[r * 129 + c + 2] = vx.z; vt[r * 129 + c + 3] = vx.w;
            }
        }
        __syncthreads();

        if (tid < 128) {
            int s = tid >> 5, tl = tid & 31;
            const float* qp = q_s + s * HD;
            const float* kp = kt + tl * 129;
            float a = 0.f;
#pragma unroll 8
            for (int dd = 0; dd < HD; dd++) a = fmaf(qp[dd], kp[dd], a);
            p_s[s * 32 + tl] = a + mask[s * TT + t0 + tl];
        }
        __syncthreads();

        if (tid < SS) {
            float mx = m_run[tid];
#pragma unroll
            for (int tl = 0; tl < 32; tl++) mx = fmaxf(mx, p_s[tid * 32 + tl]);
            scale_f[tid] = __expf(m_run[tid] - mx);
            m_run[tid] = mx;
        }
        __syncthreads();

        if (tid < 128) {
            int s = tid >> 5, tl = tid & 31;
            p_s[s * 32 + tl] = __expf(p_s[s * 32 + tl] - m_run[s]);
        }
        __syncthreads();

        if (tid < SS) {
            float sm = 0.f;
#pragma unroll
            for (int tl = 0; tl < 32; tl++) sm += p_s[tid * 32 + tl];
            l_run[tid] = l_run[tid] * scale_f[tid] + sm;
        }

        float f0 = scale_f[sb], f1 = scale_f[sb + 1];
        acc0 *= f0; acc1 *= f1;
#pragma unroll 8
        for (int tl = 0; tl < 32; tl++) {
            float v = vt[tl * 129 + d];
            acc0 = fmaf(p_s[sb * 32 + tl], v, acc0);
            acc1 = fmaf(p_s[(sb + 1) * 32 + tl], v, acc1);
        }
    }
    __syncthreads();

    // write partials (no normalization yet)
    const long pbase = ((long)(bh * NCH + ch)) * SS;
    g_pa[(pbase + sb)     * HD + d] = acc0;
    g_pa[(pbase + sb + 1) * HD + d] = acc1;
    if (tid < SS) {
        g_pm[pbase + tid] = m_run[tid];
        g_pl[pbase + tid] = l_run[tid];
    }
}

// ---------------- kernel 3b: combine split-T partials ------------------------------
__global__ void __launch_bounds__(256) attn_combine()
{
    const int idx = blockIdx.x * 256 + threadIdx.x;   // 0..131071
    const int bh = idx >> 9;          // /(SS*HD)
    const int s  = (idx >> 7) & 3;
    const int d  = idx & 127;
    const int b  = bh >> 5;
    const int h  = bh & 31;

    float M = -1e30f;
#pragma unroll
    for (int c = 0; c < NCH; c++)
        M = fmaxf(M, g_pm[((long)(bh * NCH + c)) * SS + s]);

    float num = 0.f, den = 0.f;
#pragma unroll
    for (int c = 0; c < NCH; c++) {
        long pb = ((long)(bh * NCH + c)) * SS + s;
        float w = __expf(g_pm[pb] - M);
        num = fmaf(w, g_pa[pb * HD + d], num);
        den = fmaf(w, g_pl[pb], den);
    }
    g_attn[(long)(b * SS + s) * NHHD + h * HD + d] = num / den;
}

// ---------------- kernel 4: output projection (split-K partials) -------------------
__global__ void __launch_bounds__(128) out_gemm(const float* __restrict__ wo)
{
    gemm_body(g_attn, wo, g_o2 + (long)blockIdx.y * MM * DIM, DIM,
              blockIdx.x * 64, blockIdx.y * (4096 / SPLIT), 4096 / SPLIT);
}

// ---------------- kernel 5: split-K reduce into output -----------------------------
__global__ void __launch_bounds__(256) combine_out(float* __restrict__ out)
{
    int idx = blockIdx.x * 256 + threadIdx.x;
    if (idx < MM * DIM) {
        float v = 0.f;
#pragma unroll
        for (int s = 0; s < SPLIT; s++) v += g_o2[(long)s * MM * DIM + idx];
        out[idx] = v;
    }
}

// ---------------- launch ------------------------------------------------------------
extern "C" void kernel_launch(void* const* d_in, const int* in_sizes, int n_in,
                              void* d_out, int out_size)
{
    const float* x         = (const float*)d_in[0];
    const int*   start_pos = (const int*)  d_in[1];
    const float* angles    = (const float*)d_in[2];
    const float* cache_k   = (const float*)d_in[3];
    const float* cache_v   = (const float*)d_in[4];
    const float* mask      = (const float*)d_in[5];
    const float* wq        = (const float*)d_in[6];
    const float* wk        = (const float*)d_in[7];
    const float* wv        = (const float*)d_in[8];
    const float* wo        = (const float*)d_in[9];
    const int*   layer_idx = (const int*)  d_in[10];
    float* out = (float*)d_out;

    qkv_gemm<<<dim3(96, SPLIT), 128>>>(x, wq, wk, wv);
    combine_qkv_rope<<<448, 256>>>(angles);
    attn_kernel<<<dim3(BB * NH, NCH), 256>>>(cache_k, cache_v, mask, start_pos, layer_idx);
    attn_combine<<<512, 256>>>();
    out_gemm<<<dim3(64, SPLIT), 128>>>(wo);
    combine_out<<<512, 256>>>(out);
}